// round 5
// baseline (speedup 1.0000x reference)
#include <cuda_runtime.h>
#include <cstdint>

// Problem constants (from reference): B=8, N=8192, D=256, K=3
#define BB 8
#define NN 8192
#define DD 256
#define KK 3
#define TOKENS (BB * NN)          // 65536

struct Tap { int fi, ci; float cf, cc; };

// Scratch (device globals — no allocation allowed in kernel_launch)
__device__ Tap   d_taps[TOKENS * KK];          // 3 MB
__device__ float d_Wt[KK * DD * DD];           // 768 KB: Wt[k][e][d] = weight[d][e][k]

// ---------------------------------------------------------------------------
// Kernel 1: transpose weight (D, D, K) row-major -> Wt[k][e][d]
// ---------------------------------------------------------------------------
__global__ void transpose_w_kernel(const float* __restrict__ w) {
    int idx = blockIdx.x * blockDim.x + threadIdx.x;   // idx = e*256 + d
    if (idx >= DD * DD) return;
    int d = idx & (DD - 1);
    int e = idx >> 8;
#pragma unroll
    for (int k = 0; k < KK; ++k) {
        // w[d][e][k] at ((d*DD)+e)*KK + k ; Wt[k][e][d]
        d_Wt[(k * DD + e) * DD + d] = w[((d * DD) + e) * KK + k];
    }
}

// ---------------------------------------------------------------------------
// Kernel 2: per-token tap parameters.
// One warp per token: 6 dot products of length 256, then scalar postprocess.
//   offset_k = x . ow_k ;  mod_k = sigmoid(x . mw_k)
//   pos = n + k - 1 + offset_k ; valid = 0<=pos<N
//   ff = clip(floor(pos),0,N-1); fi=int(ff); ci=min(fi+1,N-1); wc=pos-ff
//   cf = mod*valid*(1-wc); cc = mod*valid*wc
// ---------------------------------------------------------------------------
__global__ void compute_taps_kernel(const float* __restrict__ x,
                                    const float* __restrict__ ow,
                                    const float* __restrict__ mw) {
    int gw   = (blockIdx.x * blockDim.x + threadIdx.x) >> 5;  // global warp = token
    int lane = threadIdx.x & 31;
    if (gw >= TOKENS) return;

    const float* xr = x + (long long)gw * DD;
    float s0 = 0.f, s1 = 0.f, s2 = 0.f, s3 = 0.f, s4 = 0.f, s5 = 0.f;
#pragma unroll
    for (int i = 0; i < DD / 32; ++i) {
        int e = lane + (i << 5);
        float v = xr[e];
        s0 += v * __ldg(ow + e);
        s1 += v * __ldg(ow + DD + e);
        s2 += v * __ldg(ow + 2 * DD + e);
        s3 += v * __ldg(mw + e);
        s4 += v * __ldg(mw + DD + e);
        s5 += v * __ldg(mw + 2 * DD + e);
    }
#pragma unroll
    for (int off = 16; off > 0; off >>= 1) {
        s0 += __shfl_xor_sync(0xffffffffu, s0, off);
        s1 += __shfl_xor_sync(0xffffffffu, s1, off);
        s2 += __shfl_xor_sync(0xffffffffu, s2, off);
        s3 += __shfl_xor_sync(0xffffffffu, s3, off);
        s4 += __shfl_xor_sync(0xffffffffu, s4, off);
        s5 += __shfl_xor_sync(0xffffffffu, s5, off);
    }
    if (lane == 0) {
        int n = gw & (NN - 1);
        float offs[3] = { s0, s1, s2 };
        float mraw[3] = { s3, s4, s5 };
#pragma unroll
        for (int k = 0; k < KK; ++k) {
            float pos = (float)(n + k - 1) + offs[k];
            float m   = 1.0f / (1.0f + expf(-mraw[k]));
            bool valid = (pos >= 0.0f) && (pos < (float)NN);
            float ff = floorf(pos);
            ff = fminf(fmaxf(ff, 0.0f), (float)(NN - 1));
            int fi = (int)ff;
            int ci = min(fi + 1, NN - 1);
            float wc = pos - ff;
            float coef = valid ? m : 0.0f;
            Tap t;
            t.fi = fi;
            t.ci = ci;
            t.cf = coef * (1.0f - wc);
            t.cc = coef * wc;
            d_taps[gw * KK + k] = t;
        }
    }
}

// ---------------------------------------------------------------------------
// Kernel 3: fused gather + GEMM.
//   out[tok, :] = sum over contract (k,e) of modulated[tok,(k,e)] * Wt[k][e][:]
// CTA: 64 tokens x 256 outputs, contract 768 in chunks of 32.
// Inner loop uses packed fma.rn.f32x2 (full-rate fp32 on sm_103a).
// ---------------------------------------------------------------------------
#define TM 64
#define KC 32
#define NCHUNK ((KK * DD) / KC)    // 24

__global__ __launch_bounds__(256, 2)
void fused_gemm_kernel(const float* __restrict__ x, float* __restrict__ out) {
    __shared__ float As[TM][KC + 4];       // [token][e_local], stride 36 floats (144B, 16B-aligned rows)
    __shared__ float Bs[KC][DD];           // [e_local][d]
    __shared__ Tap   s_taps[TM * KK];

    const int tid  = threadIdx.x;
    const int tile = blockIdx.x;
    const int tok0 = tile * TM;                      // flattened (b*N + n) token base
    const int b    = tok0 >> 13;                     // /NN
    const float* xb = x + (long long)b * NN * DD;

    if (tid < TM * KK) s_taps[tid] = d_taps[tok0 * KK + tid];

    const int tx = tid & 15;          // 0..15  (d groups)
    const int ty = tid >> 4;          // 0..15  (token groups of 4)
    const int tx4 = tx << 2;
    const int ty4 = ty << 2;

    // A-tile loader mapping: 32 tokens per pass, 8 threads/token covering 32 e
    const int a_tok = tid >> 3;       // 0..31
    const int a_e4  = tid & 7;        // float4 slot within 32-e chunk

    // 4 m x 16 n accumulators as 8 packed f32x2 per m (zero bits == 0.0f pairs)
    unsigned long long acc2[4][8];
#pragma unroll
    for (int mi = 0; mi < 4; ++mi)
#pragma unroll
        for (int j = 0; j < 8; ++j) acc2[mi][j] = 0ull;

    __syncthreads();   // s_taps ready

    for (int chunk = 0; chunk < NCHUNK; ++chunk) {
        const int tap = chunk >> 3;              // 0..2
        const int e0  = (chunk & 7) << 5;        // 0..224

        // ---- load B chunk: Wt[tap][e0+r][d], r in [0,32), d in [0,256)
        const float* wbase = d_Wt + ((tap << 8) + e0) * DD;
#pragma unroll
        for (int it = 0; it < 8; ++it) {
            int idx = (it << 8) + tid;           // 0..2047 float4s
            int r   = idx >> 6;
            int c4  = idx & 63;
            *(float4*)&Bs[r][c4 << 2] =
                *(const float4*)(wbase + (r << 8) + (c4 << 2));
        }

        // ---- build A chunk: modulated[tok][(tap, e0..e0+31)]
#pragma unroll
        for (int p = 0; p < 2; ++p) {
            int tok = (p << 5) + a_tok;
            Tap t = s_taps[tok * KK + tap];
            const float* pf = xb + (t.fi << 8) + e0 + (a_e4 << 2);
            const float* pc = xb + (t.ci << 8) + e0 + (a_e4 << 2);
            float4 vf = *(const float4*)pf;
            float4 vc = *(const float4*)pc;
            float4 v;
            v.x = t.cf * vf.x + t.cc * vc.x;
            v.y = t.cf * vf.y + t.cc * vc.y;
            v.z = t.cf * vf.z + t.cc * vc.z;
            v.w = t.cf * vf.w + t.cc * vc.w;
            *(float4*)&As[tok][a_e4 << 2] = v;
        }
        __syncthreads();

        // ---- compute: 32 k-steps, 64 FMA/thread/step via 32 fma.rn.f32x2
#pragma unroll
        for (int kk = 0; kk < KC; ++kk) {
            unsigned long long a2[4];
#pragma unroll
            for (int mi = 0; mi < 4; ++mi) {
                float a = As[ty4 + mi][kk];
                asm("mov.b64 %0, {%1, %1};" : "=l"(a2[mi]) : "f"(a));
            }
#pragma unroll
            for (int sub = 0; sub < 4; ++sub) {
                const ulonglong2 bv =
                    *(const ulonglong2*)&Bs[kk][(sub << 6) + tx4];
#pragma unroll
                for (int mi = 0; mi < 4; ++mi) {
                    asm("fma.rn.f32x2 %0, %1, %2, %0;"
                        : "+l"(acc2[mi][sub * 2 + 0])
                        : "l"(a2[mi]), "l"(bv.x));
                    asm("fma.rn.f32x2 %0, %1, %2, %0;"
                        : "+l"(acc2[mi][sub * 2 + 1])
                        : "l"(a2[mi]), "l"(bv.y));
                }
            }
        }
        __syncthreads();
    }

    // ---- epilogue: write 4 tokens x 16 d per thread, float4 stores
#pragma unroll
    for (int mi = 0; mi < 4; ++mi) {
        long long tok = tok0 + ty4 + mi;
        float* op = out + tok * DD;
#pragma unroll
        for (int sub = 0; sub < 4; ++sub) {
            ulonglong2 v;
            v.x = acc2[mi][sub * 2 + 0];
            v.y = acc2[mi][sub * 2 + 1];
            *(ulonglong2*)(op + (sub << 6) + tx4) = v;
        }
    }
}

// ---------------------------------------------------------------------------
// Launch (graph-capturable: kernel launches only, no sync, no alloc)
// Inputs (metadata order): basic_units(B,N,D) f32, offset_w(K,D) f32,
//                          mod_w(K,D) f32, weight(D,D,K) f32. Output f32 (B,N,D).
// ---------------------------------------------------------------------------
extern "C" void kernel_launch(void* const* d_in, const int* in_sizes, int n_in,
                              void* d_out, int out_size) {
    const float* x  = (const float*)d_in[0];
    const float* ow = (const float*)d_in[1];
    const float* mw = (const float*)d_in[2];
    const float* w  = (const float*)d_in[3];
    float* out = (float*)d_out;
    (void)in_sizes; (void)n_in; (void)out_size;

    transpose_w_kernel<<<(DD * DD + 255) / 256, 256>>>(w);
    compute_taps_kernel<<<TOKENS / 8, 256>>>(x, ow, mw);     // 8 warps/block, 1 warp/token
    fused_gemm_kernel<<<TOKENS / TM, 256>>>(x, out);         // 1024 CTAs
}

// round 7
// speedup vs baseline: 1.4548x; 1.4548x over previous
#include <cuda_runtime.h>
#include <cstdint>

// Problem constants: B=8, N=8192, D=256, K=3
#define BB 8
#define NN 8192
#define DD 256
#define KK 3
#define TOKENS (BB * NN)            // 65536

#define CTA_M 128                   // tokens per CTA
#define CTA_N 128                   // output dims per CTA (2 halves of 256)
#define KC 32                       // contract chunk
#define NCHUNK 24                   // 768 / 32
#define AS_STRIDE 36                // floats; bank = 4*grp+tg -> conflict-free
#define BS_STRIDE 136               // floats; bank = 8*tg+grp -> conflict-free

struct Tap { int fi, ci; float cf, cc; };

// __device__ scratch (no allocation allowed)
__device__ Tap   d_taps[TOKENS * KK];        // 3 MB
__device__ float d_Wt[KK * DD * DD];         // 768 KB: Wt[tap*256+e][n], tf32-rounded

__device__ __forceinline__ float to_tf32(float x) {
    float r; asm("cvt.rna.tf32.f32 %0, %1;" : "=f"(r) : "f"(x)); return r;
}

__device__ __forceinline__ void mma_tf32(float* c, const uint32_t* a, const uint32_t* b) {
    asm volatile(
        "mma.sync.aligned.m16n8k8.row.col.f32.tf32.tf32.f32 "
        "{%0,%1,%2,%3}, {%4,%5,%6,%7}, {%8,%9}, {%0,%1,%2,%3};"
        : "+f"(c[0]), "+f"(c[1]), "+f"(c[2]), "+f"(c[3])
        : "r"(a[0]), "r"(a[1]), "r"(a[2]), "r"(a[3]), "r"(b[0]), "r"(b[1]));
}

// ---------------------------------------------------------------------------
// Kernel 1: B matrix build. Wt[tap*256+e][n] = tf32(weight[n][e][tap]).
// ---------------------------------------------------------------------------
__global__ void build_b_kernel(const float* __restrict__ w) {
    int idx = blockIdx.x * blockDim.x + threadIdx.x;   // (e, n)
    if (idx >= DD * DD) return;
    int n = idx & 255, e = idx >> 8;
#pragma unroll
    for (int tap = 0; tap < KK; ++tap)
        d_Wt[(tap * DD + e) * DD + n] = to_tf32(w[(n * DD + e) * KK + tap]);
}

// ---------------------------------------------------------------------------
// Kernel 2: per-token tap parameters (one warp per token).
// ---------------------------------------------------------------------------
__global__ void compute_taps_kernel(const float* __restrict__ x,
                                    const float* __restrict__ ow,
                                    const float* __restrict__ mw) {
    int gw   = (blockIdx.x * blockDim.x + threadIdx.x) >> 5;
    int lane = threadIdx.x & 31;
    if (gw >= TOKENS) return;

    const float* xr = x + (long long)gw * DD;
    float s0 = 0.f, s1 = 0.f, s2 = 0.f, s3 = 0.f, s4 = 0.f, s5 = 0.f;
#pragma unroll
    for (int i = 0; i < DD / 32; ++i) {
        int e = lane + (i << 5);
        float v = xr[e];
        s0 += v * __ldg(ow + e);
        s1 += v * __ldg(ow + DD + e);
        s2 += v * __ldg(ow + 2 * DD + e);
        s3 += v * __ldg(mw + e);
        s4 += v * __ldg(mw + DD + e);
        s5 += v * __ldg(mw + 2 * DD + e);
    }
#pragma unroll
    for (int off = 16; off > 0; off >>= 1) {
        s0 += __shfl_xor_sync(0xffffffffu, s0, off);
        s1 += __shfl_xor_sync(0xffffffffu, s1, off);
        s2 += __shfl_xor_sync(0xffffffffu, s2, off);
        s3 += __shfl_xor_sync(0xffffffffu, s3, off);
        s4 += __shfl_xor_sync(0xffffffffu, s4, off);
        s5 += __shfl_xor_sync(0xffffffffu, s5, off);
    }
    if (lane == 0) {
        int n = gw & (NN - 1);
        float offs[3] = { s0, s1, s2 };
        float mraw[3] = { s3, s4, s5 };
#pragma unroll
        for (int k = 0; k < KK; ++k) {
            float pos = (float)(n + k - 1) + offs[k];
            float m   = 1.0f / (1.0f + expf(-mraw[k]));
            bool valid = (pos >= 0.0f) && (pos < (float)NN);
            float ff = floorf(pos);
            ff = fminf(fmaxf(ff, 0.0f), (float)(NN - 1));
            int fi = (int)ff;
            int ci = min(fi + 1, NN - 1);
            float wc = pos - ff;
            float coef = valid ? m : 0.0f;
            Tap t;
            t.fi = fi; t.ci = ci;
            t.cf = coef * (1.0f - wc);
            t.cc = coef * wc;
            d_taps[gw * KK + k] = t;
        }
    }
}

// ---------------------------------------------------------------------------
// Kernel 3: fused gather + tf32 mma.sync GEMM.
// CTA: 128 tokens x 128 outputs. 8 warps = 4 (m) x 2 (n); warp tile 32x64.
// Single SMEM buffer; next chunk's global loads (A gather+interp, B copy)
// prefetched into registers while current chunk's MMAs run.
// ---------------------------------------------------------------------------
__global__ __launch_bounds__(256)
void gemm_mma_kernel(const float* __restrict__ x, float* __restrict__ out) {
    __shared__ float As[CTA_M][AS_STRIDE];
    __shared__ float Bs[KC][BS_STRIDE];
    __shared__ Tap   s_taps[CTA_M * KK];

    const int tid  = threadIdx.x;
    const int wid  = tid >> 5;
    const int lane = tid & 31;
    const int wm   = wid & 3;         // warp row (m)
    const int wn   = wid >> 2;        // warp col (n)
    const int grp  = lane >> 2;       // 0..7
    const int tg   = lane & 3;        // 0..3

    const int tile = blockIdx.x >> 1;
    const int nh   = blockIdx.x & 1;
    const int tok0 = tile * CTA_M;
    const int b    = tok0 >> 13;
    const float* xb = x + (size_t)b * NN * DD;

    // loader roles
    const int a_tok = tid >> 1;       // token for A gather (16 floats = half row)
    const int ah    = tid & 1;
    const int b_row = tid >> 3;       // B chunk row (0..31)
    const int b_cg  = tid & 7;        // B col group (16 floats)

    for (int i = tid; i < CTA_M * KK; i += 256) s_taps[i] = d_taps[tok0 * KK + i];
    __syncthreads();

    float acc[2][8][4];
#pragma unroll
    for (int mi = 0; mi < 2; ++mi)
#pragma unroll
        for (int ni = 0; ni < 8; ++ni)
#pragma unroll
            for (int j = 0; j < 4; ++j) acc[mi][ni][j] = 0.0f;

    float4 pa[4];   // prefetched interpolated A (16 floats)
    float4 pb[4];   // prefetched B (16 floats)

    // prologue: load chunk 0
    {
        Tap t = s_taps[a_tok * KK + 0];
        const float4* pf = (const float4*)(xb + t.fi * DD + ah * 16);
        const float4* pc = (const float4*)(xb + t.ci * DD + ah * 16);
#pragma unroll
        for (int j = 0; j < 4; ++j) {
            float4 vf = pf[j], vc = pc[j];
            pa[j].x = fmaf(t.cf, vf.x, t.cc * vc.x);
            pa[j].y = fmaf(t.cf, vf.y, t.cc * vc.y);
            pa[j].z = fmaf(t.cf, vf.z, t.cc * vc.z);
            pa[j].w = fmaf(t.cf, vf.w, t.cc * vc.w);
        }
        const float4* bs = (const float4*)(d_Wt + (size_t)b_row * DD + nh * 128 + b_cg * 16);
#pragma unroll
        for (int j = 0; j < 4; ++j) pb[j] = bs[j];
    }

    for (int c = 0; c < NCHUNK; ++c) {
        __syncthreads();   // previous chunk fully consumed

        // store prefetched tiles (A tf32-rounded here; B already rounded)
#pragma unroll
        for (int j = 0; j < 4; ++j) {
            float4 v;
            v.x = to_tf32(pa[j].x); v.y = to_tf32(pa[j].y);
            v.z = to_tf32(pa[j].z); v.w = to_tf32(pa[j].w);
            *(float4*)&As[a_tok][ah * 16 + j * 4] = v;
            *(float4*)&Bs[b_row][b_cg * 16 + j * 4] = pb[j];
        }
        __syncthreads();   // tiles visible

        // prefetch chunk c+1 (overlaps with MMA below)
        if (c + 1 < NCHUNK) {
            const int cn  = c + 1;
            const int tap = cn >> 3;
            const int e0  = (cn & 7) << 5;
            Tap t = s_taps[a_tok * KK + tap];
            const float4* pf = (const float4*)(xb + t.fi * DD + e0 + ah * 16);
            const float4* pc = (const float4*)(xb + t.ci * DD + e0 + ah * 16);
#pragma unroll
            for (int j = 0; j < 4; ++j) {
                float4 vf = pf[j], vc = pc[j];
                pa[j].x = fmaf(t.cf, vf.x, t.cc * vc.x);
                pa[j].y = fmaf(t.cf, vf.y, t.cc * vc.y);
                pa[j].z = fmaf(t.cf, vf.z, t.cc * vc.z);
                pa[j].w = fmaf(t.cf, vf.w, t.cc * vc.w);
            }
            const float4* bs = (const float4*)(d_Wt + ((size_t)cn * KC + b_row) * DD
                                               + nh * 128 + b_cg * 16);
#pragma unroll
            for (int j = 0; j < 4; ++j) pb[j] = bs[j];
        }

        // MMA over current chunk: 4 k-steps of 8
#pragma unroll
        for (int k0 = 0; k0 < KC; k0 += 8) {
            uint32_t afr[2][4];
#pragma unroll
            for (int mi = 0; mi < 2; ++mi) {
                int row = wm * 32 + mi * 16;
                afr[mi][0] = __float_as_uint(As[row + grp    ][k0 + tg    ]);
                afr[mi][1] = __float_as_uint(As[row + grp + 8][k0 + tg    ]);
                afr[mi][2] = __float_as_uint(As[row + grp    ][k0 + tg + 4]);
                afr[mi][3] = __float_as_uint(As[row + grp + 8][k0 + tg + 4]);
            }
            uint32_t bfr[8][2];
#pragma unroll
            for (int ni = 0; ni < 8; ++ni) {
                int col = wn * 64 + ni * 8 + grp;
                bfr[ni][0] = __float_as_uint(Bs[k0 + tg    ][col]);
                bfr[ni][1] = __float_as_uint(Bs[k0 + tg + 4][col]);
            }
#pragma unroll
            for (int mi = 0; mi < 2; ++mi)
#pragma unroll
                for (int ni = 0; ni < 8; ++ni)
                    mma_tf32(acc[mi][ni], afr[mi], bfr[ni]);
        }
    }

    // epilogue: D fragment -> out. c0/c1 at (row, 2tg), c2/c3 at (row+8, 2tg).
#pragma unroll
    for (int mi = 0; mi < 2; ++mi) {
        size_t row = (size_t)tok0 + wm * 32 + mi * 16 + grp;
        float* op0 = out + row * DD + nh * 128 + wn * 64;
        float* op1 = op0 + 8 * DD;
#pragma unroll
        for (int ni = 0; ni < 8; ++ni) {
            int col = ni * 8 + tg * 2;
            float2 v0 = { acc[mi][ni][0], acc[mi][ni][1] };
            float2 v1 = { acc[mi][ni][2], acc[mi][ni][3] };
            *(float2*)(op0 + col) = v0;
            *(float2*)(op1 + col) = v1;
        }
    }
}

// ---------------------------------------------------------------------------
// Launch (graph-capturable: kernel launches only)
// ---------------------------------------------------------------------------
extern "C" void kernel_launch(void* const* d_in, const int* in_sizes, int n_in,
                              void* d_out, int out_size) {
    const float* x  = (const float*)d_in[0];
    const float* ow = (const float*)d_in[1];
    const float* mw = (const float*)d_in[2];
    const float* w  = (const float*)d_in[3];
    float* out = (float*)d_out;
    (void)in_sizes; (void)n_in; (void)out_size;

    build_b_kernel<<<(DD * DD + 255) / 256, 256>>>(w);
    compute_taps_kernel<<<TOKENS / 8, 256>>>(x, ow, mw);
    gemm_mma_kernel<<<(TOKENS / CTA_M) * 2, 256>>>(x, out);
}

// round 8
// speedup vs baseline: 2.4828x; 1.7066x over previous
#include <cuda_runtime.h>
#include <cuda_fp16.h>
#include <cstdint>

// Problem constants: B=8, N=8192, D=256, K=3
#define BB 8
#define NN 8192
#define DD 256
#define KK 3
#define TOKENS (BB * NN)            // 65536

#define CTA_M 128                   // tokens per CTA
#define KC 32                       // contract chunk (2 k16 steps)
#define NCHUNK 24                   // 768 / 32
#define S_STRIDE 40                 // halves; bank = (row*20 + tg) % 32, conflict-free

struct Tap { int fi, ci; float cf, cc; };

// __device__ scratch (no allocation allowed)
__device__ Tap    d_taps[TOKENS * KK];        // 3 MB
__device__ __half d_Wh[DD * KK * DD];         // 384 KB: d_Wh[n][tap*256+e] = half(w[n][e][tap])

__device__ __forceinline__ void mma_f16(float* c, const uint32_t* a,
                                        uint32_t b0, uint32_t b1) {
    asm volatile(
        "mma.sync.aligned.m16n8k16.row.col.f32.f16.f16.f32 "
        "{%0,%1,%2,%3}, {%4,%5,%6,%7}, {%8,%9}, {%0,%1,%2,%3};"
        : "+f"(c[0]), "+f"(c[1]), "+f"(c[2]), "+f"(c[3])
        : "r"(a[0]), "r"(a[1]), "r"(a[2]), "r"(a[3]), "r"(b0), "r"(b1));
}

// ---------------------------------------------------------------------------
// Kernel 1: B matrix build. d_Wh[n*768 + tap*256 + e] = half(weight[n][e][tap]).
// ---------------------------------------------------------------------------
__global__ void build_b_kernel(const float* __restrict__ w) {
    int idx = blockIdx.x * blockDim.x + threadIdx.x;   // (n, e)
    if (idx >= DD * DD) return;
    int n = idx >> 8, e = idx & 255;
#pragma unroll
    for (int tap = 0; tap < KK; ++tap)
        d_Wh[n * (KK * DD) + tap * DD + e] = __float2half(w[(n * DD + e) * KK + tap]);
}

// ---------------------------------------------------------------------------
// Kernel 2: per-token tap parameters (one warp per token).
// ---------------------------------------------------------------------------
__global__ void compute_taps_kernel(const float* __restrict__ x,
                                    const float* __restrict__ ow,
                                    const float* __restrict__ mw) {
    int gw   = (blockIdx.x * blockDim.x + threadIdx.x) >> 5;
    int lane = threadIdx.x & 31;
    if (gw >= TOKENS) return;

    const float* xr = x + (long long)gw * DD;
    float s0 = 0.f, s1 = 0.f, s2 = 0.f, s3 = 0.f, s4 = 0.f, s5 = 0.f;
#pragma unroll
    for (int i = 0; i < DD / 32; ++i) {
        int e = lane + (i << 5);
        float v = xr[e];
        s0 += v * __ldg(ow + e);
        s1 += v * __ldg(ow + DD + e);
        s2 += v * __ldg(ow + 2 * DD + e);
        s3 += v * __ldg(mw + e);
        s4 += v * __ldg(mw + DD + e);
        s5 += v * __ldg(mw + 2 * DD + e);
    }
#pragma unroll
    for (int off = 16; off > 0; off >>= 1) {
        s0 += __shfl_xor_sync(0xffffffffu, s0, off);
        s1 += __shfl_xor_sync(0xffffffffu, s1, off);
        s2 += __shfl_xor_sync(0xffffffffu, s2, off);
        s3 += __shfl_xor_sync(0xffffffffu, s3, off);
        s4 += __shfl_xor_sync(0xffffffffu, s4, off);
        s5 += __shfl_xor_sync(0xffffffffu, s5, off);
    }
    if (lane == 0) {
        int n = gw & (NN - 1);
        float offs[3] = { s0, s1, s2 };
        float mraw[3] = { s3, s4, s5 };
#pragma unroll
        for (int k = 0; k < KK; ++k) {
            float pos = (float)(n + k - 1) + offs[k];
            float m   = 1.0f / (1.0f + expf(-mraw[k]));
            bool valid = (pos >= 0.0f) && (pos < (float)NN);
            float ff = floorf(pos);
            ff = fminf(fmaxf(ff, 0.0f), (float)(NN - 1));
            int fi = (int)ff;
            int ci = min(fi + 1, NN - 1);
            float wc = pos - ff;
            float coef = valid ? m : 0.0f;
            Tap t;
            t.fi = fi; t.ci = ci;
            t.cf = coef * (1.0f - wc);
            t.cc = coef * wc;
            d_taps[gw * KK + k] = t;
        }
    }
}

// ---------------------------------------------------------------------------
// Kernel 3: fused gather + fp16 mma.sync (m16n8k16, fp32 accumulate).
// CTA: 128 tokens x 128 outputs (2 n-halves via grid). 8 warps = 4m x 2n,
// warp tile 32x64. Register prefetch of next chunk overlaps current MMAs.
// SMEM half layout, stride 40 halves: A[m][k], B[n][k] (k-pairs = half2).
// ---------------------------------------------------------------------------
__global__ __launch_bounds__(256, 2)
void gemm_mma_kernel(const float* __restrict__ x, float* __restrict__ out) {
    __shared__ __half As[CTA_M * S_STRIDE];   // [token][k_local]
    __shared__ __half Bs[128 * S_STRIDE];     // [n_local][k_local]
    __shared__ Tap    s_taps[CTA_M * KK];

    const int tid  = threadIdx.x;
    const int wid  = tid >> 5;
    const int lane = tid & 31;
    const int wm   = wid & 3;         // warp row (m)
    const int wn   = wid >> 2;        // warp col (n)
    const int grp  = lane >> 2;       // 0..7
    const int tg   = lane & 3;        // 0..3

    const int tile = blockIdx.x >> 1;
    const int nh   = blockIdx.x & 1;
    const int tok0 = tile * CTA_M;
    const int b    = tok0 >> 13;
    const float* xb = x + (size_t)b * NN * DD;

    // loader roles: 128 rows, 2 threads/row (16 elements each)
    const int a_tok = tid >> 1;
    const int ah    = tid & 1;

    for (int i = tid; i < CTA_M * KK; i += 256) s_taps[i] = d_taps[tok0 * KK + i];
    __syncthreads();

    float acc[2][8][4];
#pragma unroll
    for (int mi = 0; mi < 2; ++mi)
#pragma unroll
        for (int ni = 0; ni < 8; ++ni)
#pragma unroll
            for (int j = 0; j < 4; ++j) acc[mi][ni][j] = 0.0f;

    float4 pa[4];     // prefetched interpolated A (16 f32)
    uint4  pb[2];     // prefetched B (16 halves)

    const __half* whb = d_Wh + (size_t)(nh * 128 + a_tok) * (KK * DD) + ah * 16;

    // prologue: chunk 0
    {
        Tap t = s_taps[a_tok * KK + 0];
        const float4* pf = (const float4*)(xb + t.fi * DD + ah * 16);
        const float4* pc = (const float4*)(xb + t.ci * DD + ah * 16);
#pragma unroll
        for (int j = 0; j < 4; ++j) {
            float4 vf = pf[j], vc = pc[j];
            pa[j].x = fmaf(t.cf, vf.x, t.cc * vc.x);
            pa[j].y = fmaf(t.cf, vf.y, t.cc * vc.y);
            pa[j].z = fmaf(t.cf, vf.z, t.cc * vc.z);
            pa[j].w = fmaf(t.cf, vf.w, t.cc * vc.w);
        }
        const uint4* bs = (const uint4*)whb;    // chunk 0 offset = 0
        pb[0] = bs[0]; pb[1] = bs[1];
    }

    for (int c = 0; c < NCHUNK; ++c) {
        __syncthreads();   // previous chunk fully consumed

        // store prefetched tiles (A converted f32 -> half2 here)
        {
            uint4 ha;
            __half2* hp = (__half2*)&ha;
            hp[0] = __floats2half2_rn(pa[0].x, pa[0].y);
            hp[1] = __floats2half2_rn(pa[0].z, pa[0].w);
            hp[2] = __floats2half2_rn(pa[1].x, pa[1].y);
            hp[3] = __floats2half2_rn(pa[1].z, pa[1].w);
            *(uint4*)&As[a_tok * S_STRIDE + ah * 16] = ha;
            hp[0] = __floats2half2_rn(pa[2].x, pa[2].y);
            hp[1] = __floats2half2_rn(pa[2].z, pa[2].w);
            hp[2] = __floats2half2_rn(pa[3].x, pa[3].y);
            hp[3] = __floats2half2_rn(pa[3].z, pa[3].w);
            *(uint4*)&As[a_tok * S_STRIDE + ah * 16 + 8] = ha;
            *(uint4*)&Bs[a_tok * S_STRIDE + ah * 16] = pb[0];
            *(uint4*)&Bs[a_tok * S_STRIDE + ah * 16 + 8] = pb[1];
        }
        __syncthreads();   // tiles visible

        // prefetch chunk c+1 (overlaps MMA below)
        if (c + 1 < NCHUNK) {
            const int cn  = c + 1;
            const int tap = cn >> 3;
            const int e0  = (cn & 7) << 5;
            Tap t = s_taps[a_tok * KK + tap];
            const float4* pf = (const float4*)(xb + t.fi * DD + e0 + ah * 16);
            const float4* pc = (const float4*)(xb + t.ci * DD + e0 + ah * 16);
#pragma unroll
            for (int j = 0; j < 4; ++j) {
                float4 vf = pf[j], vc = pc[j];
                pa[j].x = fmaf(t.cf, vf.x, t.cc * vc.x);
                pa[j].y = fmaf(t.cf, vf.y, t.cc * vc.y);
                pa[j].z = fmaf(t.cf, vf.z, t.cc * vc.z);
                pa[j].w = fmaf(t.cf, vf.w, t.cc * vc.w);
            }
            const uint4* bs = (const uint4*)(whb + cn * KC);
            pb[0] = bs[0]; pb[1] = bs[1];
        }

        // MMA over current chunk: 2 k16 steps
#pragma unroll
        for (int ks = 0; ks < 2; ++ks) {
            const int k0 = ks * 16;
            uint32_t afr[2][4];
#pragma unroll
            for (int mi = 0; mi < 2; ++mi) {
                int row = wm * 32 + mi * 16;
                afr[mi][0] = *(const uint32_t*)&As[(row + grp    ) * S_STRIDE + k0 + 2 * tg    ];
                afr[mi][1] = *(const uint32_t*)&As[(row + grp + 8) * S_STRIDE + k0 + 2 * tg    ];
                afr[mi][2] = *(const uint32_t*)&As[(row + grp    ) * S_STRIDE + k0 + 2 * tg + 8];
                afr[mi][3] = *(const uint32_t*)&As[(row + grp + 8) * S_STRIDE + k0 + 2 * tg + 8];
            }
#pragma unroll
            for (int ni = 0; ni < 8; ++ni) {
                int col = wn * 64 + ni * 8 + grp;
                uint32_t b0 = *(const uint32_t*)&Bs[col * S_STRIDE + k0 + 2 * tg    ];
                uint32_t b1 = *(const uint32_t*)&Bs[col * S_STRIDE + k0 + 2 * tg + 8];
                mma_f16(acc[0][ni], afr[0], b0, b1);
                mma_f16(acc[1][ni], afr[1], b0, b1);
            }
        }
    }

    // epilogue: c0/c1 at (row, 2tg), c2/c3 at (row+8, 2tg)
#pragma unroll
    for (int mi = 0; mi < 2; ++mi) {
        size_t row = (size_t)tok0 + wm * 32 + mi * 16 + grp;
        float* op0 = out + row * DD + nh * 128 + wn * 64;
        float* op1 = op0 + 8 * DD;
#pragma unroll
        for (int ni = 0; ni < 8; ++ni) {
            int col = ni * 8 + tg * 2;
            float2 v0 = { acc[mi][ni][0], acc[mi][ni][1] };
            float2 v1 = { acc[mi][ni][2], acc[mi][ni][3] };
            *(float2*)(op0 + col) = v0;
            *(float2*)(op1 + col) = v1;
        }
    }
}

// ---------------------------------------------------------------------------
// Launch (graph-capturable: kernel launches only)
// ---------------------------------------------------------------------------
extern "C" void kernel_launch(void* const* d_in, const int* in_sizes, int n_in,
                              void* d_out, int out_size) {
    const float* x  = (const float*)d_in[0];
    const float* ow = (const float*)d_in[1];
    const float* mw = (const float*)d_in[2];
    const float* w  = (const float*)d_in[3];
    float* out = (float*)d_out;
    (void)in_sizes; (void)n_in; (void)out_size;

    build_b_kernel<<<(DD * DD + 255) / 256, 256>>>(w);
    compute_taps_kernel<<<TOKENS / 8, 256>>>(x, ow, mw);
    gemm_mma_kernel<<<(TOKENS / CTA_M) * 2, 256>>>(x, out);
}